// round 1
// baseline (speedup 1.0000x reference)
#include <cuda_runtime.h>

#define HH 1024
#define WW 1024
#define HW (HH*WW)
#define NT 256
#define NB2 592   // grid for gradu kernel (4 blocks/SM on 148 SMs)

// ---------------- device scratch (no cudaMalloc allowed) ----------------
__device__ float g_rhoc[HW];
__device__ float g_gi0[HW];
__device__ float g_gi1[HW];
__device__ float g_norm[HW];
__device__ float g_u[2*HW];      // [component][HW]
__device__ float g_P[4][HW];     // P[i][j] flattened: k = i*2+j  (i=gradu batch/component, j=filter)
__device__ float g_G[4][HW];     // G[k] = filter_j(u_i), same flattening
__device__ float g_partial[NB2];
__device__ unsigned int g_count;
__device__ float g_S;

// ---------------- K0: precompute rho_c, grad_im, norm_grad; zero u,p ----------------
__global__ void k_init(const float* __restrict__ x, const float* __restrict__ gw) {
    int idx = blockIdx.x * NT + threadIdx.x;
    if (idx >= HW) return;
    int y = idx >> 10, xx = idx & (WW - 1);
    const float* __restrict__ x1 = x + HW;

    g_rhoc[idx] = x1[idx] - x[idx];

    float a = 0.f, b = 0.f;
    #pragma unroll
    for (int dy = -1; dy <= 1; dy++) {
        #pragma unroll
        for (int dx = -1; dx <= 1; dx++) {
            int yy = y + dy, xc = xx + dx;
            float v = (yy >= 0 && yy < HH && xc >= 0 && xc < WW) ? x1[yy * WW + xc] : 0.f;
            int k = (dy + 1) * 3 + (dx + 1);
            a += v * __ldg(&gw[k]);
            b += v * __ldg(&gw[9 + k]);
        }
    }
    g_gi0[idx] = a;
    g_gi1[idx] = b;
    g_norm[idx] = a * a + b * b;

    g_u[idx] = 0.f; g_u[HW + idx] = 0.f;
    g_P[0][idx] = 0.f; g_P[1][idx] = 0.f; g_P[2][idx] = 0.f; g_P[3][idx] = 0.f;
    if (idx == 0) g_count = 0u;
}

// ---------------- K1: u update (pointwise thresholding + divergence of p) ----------------
// In-place safe: reads of u are at own pixel only.
__global__ void k_update_u(const float* __restrict__ wx, const float* __restrict__ wy,
                           const float* __restrict__ lam, const float* __restrict__ theta_p,
                           float* __restrict__ out) {
    int idx = blockIdx.x * NT + threadIdx.x;
    if (idx >= HW) return;

    float theta = __ldg(theta_p);
    float tl = theta * __ldg(lam);
    float wx0 = __ldg(&wx[0]), wx1 = __ldg(&wx[1]);
    float wy0 = __ldg(&wy[0]), wy1 = __ldg(&wy[1]);

    int xx = idx & (WW - 1);
    int y  = idx >> 10;

    float u0 = g_u[idx], u1 = g_u[HW + idx];
    float gi0 = g_gi0[idx], gi1 = g_gi1[idx];
    float nrm = g_norm[idx];
    float rho = g_rhoc[idx] + gi0 * u0 + gi1 * u1;
    float a = fabsf(rho);
    float thv = tl * nrm;

    float v0 = u0, v1 = u1;
    if (a < thv) {                       // thv > a >= 0 implies nrm > 0: division safe
        float q = rho / nrm;
        v0 -= q * gi0; v1 -= q * gi1;
    } else if (a > thv) {
        float s = (rho > 0.f) ? 1.f : ((rho < 0.f) ? -1.f : 0.f);
        float c = tl * s;
        v0 -= c * gi0; v1 -= c * gi1;
    }

    // div_x(P[0][c]) + div_y(P[1][c]), zero-padded on the left/top
    float p00 = g_P[0][idx], p01 = g_P[1][idx], p10 = g_P[2][idx], p11 = g_P[3][idx];
    float p00l = (xx > 0) ? g_P[0][idx - 1]  : 0.f;
    float p01l = (xx > 0) ? g_P[1][idx - 1]  : 0.f;
    float p10u = (y  > 0) ? g_P[2][idx - WW] : 0.f;
    float p11u = (y  > 0) ? g_P[3][idx - WW] : 0.f;

    float d0 = p00l * wx0 + p00 * wx1 + p10u * wy0 + p10 * wy1;
    float d1 = p01l * wx0 + p01 * wx1 + p11u * wy0 + p11 * wy1;

    out[idx]      = v0 + theta * d0;
    out[HW + idx] = v1 + theta * d1;
}

// ---------------- K2: gradu = 3x3 Sobel of u (both components) + deterministic global |.| sum ----------------
__global__ void k_gradu(const float* __restrict__ gw) {
    float wgt[18];
    #pragma unroll
    for (int i = 0; i < 18; i++) wgt[i] = __ldg(&gw[i]);

    float acc = 0.f;
    int stride = gridDim.x * NT;
    for (int idx = blockIdx.x * NT + threadIdx.x; idx < HW; idx += stride) {
        int y = idx >> 10, xx = idx & (WW - 1);
        float s00 = 0.f, s01 = 0.f, s10 = 0.f, s11 = 0.f;
        #pragma unroll
        for (int dy = -1; dy <= 1; dy++) {
            #pragma unroll
            for (int dx = -1; dx <= 1; dx++) {
                int yy = y + dy, xc = xx + dx;
                bool in = (yy >= 0 && yy < HH && xc >= 0 && xc < WW);
                int o = yy * WW + xc;
                float v0 = in ? g_u[o]      : 0.f;
                float v1 = in ? g_u[HW + o] : 0.f;
                int k = (dy + 1) * 3 + (dx + 1);
                float wa = wgt[k], wb = wgt[9 + k];
                s00 += v0 * wa; s01 += v0 * wb;
                s10 += v1 * wa; s11 += v1 * wb;
            }
        }
        g_G[0][idx] = s00; g_G[1][idx] = s01; g_G[2][idx] = s10; g_G[3][idx] = s11;
        acc += fabsf(s00) + fabsf(s01) + fabsf(s10) + fabsf(s11);
    }

    // block tree reduction (deterministic)
    __shared__ float sm[NT];
    int tid = threadIdx.x;
    sm[tid] = acc;
    __syncthreads();
    for (int s = NT / 2; s > 0; s >>= 1) {
        if (tid < s) sm[tid] += sm[tid + s];
        __syncthreads();
    }

    // last-block-done: final sum in a fixed order (deterministic across runs)
    __shared__ bool isLast;
    if (tid == 0) {
        g_partial[blockIdx.x] = sm[0];
        __threadfence();
        unsigned prev = atomicAdd(&g_count, 1u);
        isLast = (prev == gridDim.x - 1);
    }
    __syncthreads();
    if (isLast && tid < 32) {
        float s = 0.f;
        for (int i = tid; i < (int)gridDim.x; i += 32) s += g_partial[i];
        #pragma unroll
        for (int o = 16; o > 0; o >>= 1) s += __shfl_down_sync(0xffffffffu, s, o);
        if (tid == 0) { g_S = s; g_count = 0u; }
    }
}

// ---------------- K3: p update (pointwise, in place) ----------------
__global__ void k_update_p(const float* __restrict__ tau_p, const float* __restrict__ theta_p) {
    int idx = blockIdx.x * NT + threadIdx.x;
    if (idx >= HW) return;
    float r = __ldg(tau_p) / __ldg(theta_p);
    float inv = 1.f / (1.f + r * g_S);
    #pragma unroll
    for (int k = 0; k < 4; k++)
        g_P[k][idx] = (g_P[k][idx] + r * g_G[k][idx]) * inv;
}

// ---------------- launch ----------------
extern "C" void kernel_launch(void* const* d_in, const int* in_sizes, int n_in,
                              void* d_out, int out_size) {
    const float* x   = (const float*)d_in[0];
    const float* gw  = (const float*)d_in[1];
    const float* wx  = (const float*)d_in[2];
    const float* wy  = (const float*)d_in[3];
    const float* lam = (const float*)d_in[4];
    const float* tau = (const float*)d_in[5];
    const float* th  = (const float*)d_in[6];
    float* out = (float*)d_out;

    float* u_dev = nullptr;
    cudaGetSymbolAddress((void**)&u_dev, g_u);   // query only, capture-safe

    const int nb = HW / NT;   // 4096 blocks

    k_init<<<nb, NT>>>(x, gw);
    for (int t = 0; t < 10; t++) {
        float* dst = (t == 9) ? out : u_dev;     // final iteration writes straight to d_out
        k_update_u<<<nb, NT>>>(wx, wy, lam, th, dst);
        if (t < 9) {                             // iteration 10's gradu/p are dead code
            k_gradu<<<NB2, NT>>>(gw);
            k_update_p<<<nb, NT>>>(tau, th);
        }
    }
}